// round 17
// baseline (speedup 1.0000x reference)
#include <cuda_runtime.h>
#include <cuda_bf16.h>

#define BB 4096
#define TT 512
#define BPC 32          // batches per scan CTA

typedef unsigned long long u64;
typedef unsigned int u32;

// 1 GiB scratch for gate pre-activations: [B][T][128] fp32 (g*32+j, g:f,i,o,z)
__device__ float g_proj[(size_t)BB * TT * 128];

__device__ __forceinline__ u32 smem_u32(const void* p) {
    u32 a;
    asm("{ .reg .u64 t; cvta.to.shared.u64 t, %1; cvt.u32.u64 %0, t; }"
        : "=r"(a) : "l"(p));
    return a;
}
__device__ __forceinline__ u32 swz(u32 off) { return off ^ ((off >> 3) & 0x70); }
__device__ __forceinline__ void cp16(u32 dst, const void* src) {
    asm volatile("cp.async.ca.shared.global [%0], [%1], 16;"
                 :: "r"(dst), "l"(src) : "memory");
}
__device__ __forceinline__ float tanh_hw(float x) {
    float r; asm("tanh.approx.f32 %0, %1;" : "=f"(r) : "f"(x)); return r;
}
__device__ __forceinline__ void ldsm4(u32 &r0, u32 &r1, u32 &r2, u32 &r3, u32 a) {
    asm volatile("ldmatrix.sync.aligned.m8n8.x4.shared.b16 {%0,%1,%2,%3}, [%4];"
                 : "=r"(r0), "=r"(r1), "=r"(r2), "=r"(r3) : "r"(a));
}
__device__ __forceinline__ void mma16816(float* c, const u32* a, u32 b0, u32 b1) {
    asm volatile(
        "mma.sync.aligned.m16n8k16.row.col.f32.bf16.bf16.f32 "
        "{%0,%1,%2,%3}, {%4,%5,%6,%7}, {%8,%9}, {%0,%1,%2,%3};"
        : "+f"(c[0]), "+f"(c[1]), "+f"(c[2]), "+f"(c[3])
        : "r"(a[0]), "r"(a[1]), "r"(a[2]), "r"(a[3]), "r"(b0), "r"(b1));
}

// =====================================================================
// Phase 1: proj (R5 kernel, verbatim — proven 7.4e-7 path)
// =====================================================================
#define PJ_SMEM 99328
#define A_OFF(buf, hl) (1024 + (buf) * 32768 + (hl) * 16384)
#define BH_OFF 66560
#define BL_OFF 82944

__global__ void __launch_bounds__(256) proj_mma(
    const float* __restrict__ x,
    const float* __restrict__ wf, const float* __restrict__ wfb,
    const float* __restrict__ wi, const float* __restrict__ wib,
    const float* __restrict__ wo, const float* __restrict__ wob,
    const float* __restrict__ wz, const float* __restrict__ wzb)
{
    extern __shared__ __align__(1024) char sm[];
    float* bs = (float*)sm;
    const int tid = threadIdx.x;
    const int wid = tid >> 5, lane = tid & 31;
    const u32 sb = smem_u32(sm);

    for (int i = tid; i < 4096; i += 256) {
        int n = i >> 5, kp = i & 31;
        int g = n >> 5, j = n & 31;
        const float* wp = (g == 0) ? wf : (g == 1) ? wi : (g == 2) ? wo : wz;
        float a = wp[j * 64 + kp * 2], b = wp[j * 64 + kp * 2 + 1];
        __nv_bfloat162 h = __floats2bfloat162_rn(a, b);
        float ha = __bfloat162float(h.x), hb = __bfloat162float(h.y);
        __nv_bfloat162 l = __floats2bfloat162_rn(a - ha, b - hb);
        u32 off = swz((u32)(n * 128 + kp * 4));
        *(u32*)(sm + BH_OFF + off) = *(u32*)&h;
        *(u32*)(sm + BL_OFF + off) = *(u32*)&l;
    }
    if (tid < 128) {
        int g = tid >> 5, j = tid & 31;
        const float* bb = (g == 0) ? wfb : (g == 1) ? wib : (g == 2) ? wob : wzb;
        bs[tid] = bb[j];
    }

    const size_t tile0 = (size_t)blockIdx.x * 8;

    auto stage_ld = [&](size_t tile, int half, float4* v) {
        const float4* X4 = (const float4*)x + tile * 2048 + half * 1024;
        #pragma unroll
        for (int q = 0; q < 4; ++q) v[q] = X4[q * 256 + tid];
    };
    auto stage_st = [&](int buf, int half, const float4* v) {
        char* ah = sm + A_OFF(buf, 0);
        char* al = sm + A_OFF(buf, 1);
        #pragma unroll
        for (int q = 0; q < 4; ++q) {
            int i = half * 1024 + q * 256 + tid;
            float4 w = v[q];
            int r = i >> 4, c4 = i & 15;
            __nv_bfloat162 h0 = __floats2bfloat162_rn(w.x, w.y);
            __nv_bfloat162 h1 = __floats2bfloat162_rn(w.z, w.w);
            float r0 = w.x - __bfloat162float(h0.x);
            float r1 = w.y - __bfloat162float(h0.y);
            float r2 = w.z - __bfloat162float(h1.x);
            float r3 = w.w - __bfloat162float(h1.y);
            __nv_bfloat162 l0 = __floats2bfloat162_rn(r0, r1);
            __nv_bfloat162 l1 = __floats2bfloat162_rn(r2, r3);
            u32 off = swz((u32)(r * 128 + c4 * 8));
            *(u64*)(ah + off) = (u64)(*(u32*)&h0) | ((u64)(*(u32*)&h1) << 32);
            *(u64*)(al + off) = (u64)(*(u32*)&l0) | ((u64)(*(u32*)&l1) << 32);
        }
    };

    float4 v[4];
    stage_ld(tile0, 0, v); stage_st(0, 0, v);
    stage_ld(tile0, 1, v); stage_st(0, 1, v);
    __syncthreads();

    const int mwarp = wid & 3, nwarp = wid >> 2;
    const int arow_l = lane & 15, acol_l = (lane >> 4) * 16;
    const int brow_l = (lane & 7) + ((lane >> 4) << 3);
    const int bcol_l = ((lane >> 3) & 1) * 16;

    auto pass = [&](float acc[2][8][4], u32 abase, u32 bbase) {
        #pragma unroll
        for (int s = 0; s < 4; ++s) {
            u32 a[2][4];
            #pragma unroll
            for (int mt = 0; mt < 2; ++mt) {
                int row = mwarp * 32 + mt * 16 + arow_l;
                ldsm4(a[mt][0], a[mt][1], a[mt][2], a[mt][3],
                      abase + swz((u32)(row * 128 + s * 32 + acol_l)));
            }
            u32 b[8][2];
            #pragma unroll
            for (int nb = 0; nb < 4; ++nb) {
                int row = nwarp * 64 + nb * 16 + brow_l;
                ldsm4(b[nb * 2][0], b[nb * 2][1], b[nb * 2 + 1][0], b[nb * 2 + 1][1],
                      bbase + swz((u32)(row * 128 + s * 32 + bcol_l)));
            }
            #pragma unroll
            for (int mt = 0; mt < 2; ++mt)
                #pragma unroll
                for (int nt = 0; nt < 8; ++nt)
                    mma16816(acc[mt][nt], a[mt], b[nt][0], b[nt][1]);
        }
    };

    for (int t = 0; t < 8; ++t) {
        const int buf = t & 1;
        float acc[2][8][4];
        #pragma unroll
        for (int mt = 0; mt < 2; ++mt)
            #pragma unroll
            for (int nt = 0; nt < 8; ++nt)
                #pragma unroll
                for (int q = 0; q < 4; ++q) acc[mt][nt][q] = 0.f;

        const u32 ah = sb + A_OFF(buf, 0);
        const u32 al = sb + A_OFF(buf, 1);

        if (t < 7) stage_ld(tile0 + t + 1, 0, v);
        pass(acc, ah, sb + BH_OFF);
        if (t < 7) { stage_st(buf ^ 1, 0, v); stage_ld(tile0 + t + 1, 1, v); }
        pass(acc, al, sb + BH_OFF);
        if (t < 7) stage_st(buf ^ 1, 1, v);
        pass(acc, ah, sb + BL_OFF);

        const size_t rowbase = (tile0 + t) * 128 + mwarp * 32;
        const int colb = nwarp * 64;
        #pragma unroll
        for (int mt = 0; mt < 2; ++mt) {
            const size_t r0 = rowbase + mt * 16 + (lane >> 2);
            #pragma unroll
            for (int nt = 0; nt < 8; ++nt) {
                int col = colb + nt * 8 + (lane & 3) * 2;
                float b0v = bs[col], b1v = bs[col + 1];
                float2 dlo = make_float2(acc[mt][nt][0] + b0v, acc[mt][nt][1] + b1v);
                float2 dhi = make_float2(acc[mt][nt][2] + b0v, acc[mt][nt][3] + b1v);
                *(float2*)(g_proj + r0 * 128 + col)       = dlo;
                *(float2*)(g_proj + (r0 + 8) * 128 + col) = dhi;
            }
        }
        __syncthreads();
    }
}

// =====================================================================
// Phase 2: HMMA-batched scan. Grid 128 (single wave), 4 warps = 4 gates,
// 32 batches/CTA. pre_g = X_g + H(bf16 hi/lo) @ R_g^T via 48 HMMA/warp/step.
// =====================================================================
// smem: XS 4 x [32][132] f32 | PRE [4][32][36] f32 | H hi/lo [32][80B]
#define XS     0
#define XSLOT  16896
#define PRE    67584
#define HHI    86016
#define HLO    88576
#define SC_SMEM 91136

__global__ void __launch_bounds__(128) scan_hmma(
    const float* __restrict__ rf, const float* __restrict__ ri,
    const float* __restrict__ ro, const float* __restrict__ rz,
    const void*  __restrict__ tick, const float* __restrict__ emb,
    const float* __restrict__ fcw, const float* __restrict__ fcb,
    float* __restrict__ out)
{
    extern __shared__ __align__(1024) char sm[];
    const int tid = threadIdx.x;
    const int w = tid >> 5, lane = tid & 31;
    const u32 sb = smem_u32(sm);
    const int bat0 = blockIdx.x * BPC;

    // ---- B-frags: R_g bf16 hi/lo, register-resident ----
    const float* Rg = (w == 0) ? rf : (w == 1) ? ri : (w == 2) ? ro : rz;
    u32 Bh[2][4][2], Bl[2][4][2];           // [k16][n8][k-half]
    #pragma unroll
    for (int ks = 0; ks < 2; ++ks)
        #pragma unroll
        for (int nt = 0; nt < 4; ++nt)
            #pragma unroll
            for (int r = 0; r < 2; ++r) {
                int n = nt * 8 + (lane >> 2);
                int k = ks * 16 + r * 8 + (lane & 3) * 2;
                float a = Rg[n * 32 + k], b = Rg[n * 32 + k + 1];
                __nv_bfloat162 hi = __floats2bfloat162_rn(a, b);
                __nv_bfloat162 lo = __floats2bfloat162_rn(
                    a - __bfloat162float(hi.x), b - __bfloat162float(hi.y));
                Bh[ks][nt][r] = *(u32*)&hi;
                Bl[ks][nt][r] = *(u32*)&lo;
            }

    // ---- zero H (h0 = 0), prologue cp.async ----
    for (int i = tid; i < 1280; i += 128) ((u32*)(sm + HHI))[i] = 0u;

    auto ldx = [&](int slot, int t) {
        #pragma unroll
        for (int q = 0; q < 8; ++q) {
            int idx = q * 128 + tid;
            int b = idx >> 5, c4 = idx & 31;
            const float4* src = (const float4*)g_proj
                              + ((size_t)(bat0 + b) * TT + t) * 32 + c4;
            cp16(sb + XS + slot * XSLOT + b * 528 + c4 * 16, src);
        }
        asm volatile("cp.async.commit_group;" ::: "memory");
    };
    #pragma unroll
    for (int s = 0; s < 4; ++s) ldx(s, s);
    asm volatile("cp.async.wait_group 3;" ::: "memory");
    __syncthreads();

    float cst[8], nst[8], h[8];
    #pragma unroll
    for (int e = 0; e < 8; ++e) { cst[e] = 0.f; nst[e] = 0.f; h[e] = 0.f; }
    const int b_ep = w * 8 + (lane >> 2);
    const int j0 = (lane & 3) * 8;
    float* pref = (float*)(sm + PRE);

    for (int t = 0; t < TT; ++t) {
        const int slot = t & 3;

        // A-frags from H (bf16 hi/lo, 80B rows)
        u32 Ah[2][2][4], Al[2][2][4];
        #pragma unroll
        for (int mt = 0; mt < 2; ++mt)
            #pragma unroll
            for (int ks = 0; ks < 2; ++ks) {
                u32 off = (u32)((mt * 16 + (lane & 15)) * 80 + ks * 32 + ((lane >> 4) << 4));
                ldsm4(Ah[mt][ks][0], Ah[mt][ks][1], Ah[mt][ks][2], Ah[mt][ks][3],
                      sb + HHI + off);
                ldsm4(Al[mt][ks][0], Al[mt][ks][1], Al[mt][ks][2], Al[mt][ks][3],
                      sb + HLO + off);
            }

        // C-init = X_g (from cp.async'd slot; includes bias)
        float acc[2][4][4];
        const float* XSf = (const float*)(sm + XS) + slot * 4224;
        #pragma unroll
        for (int mt = 0; mt < 2; ++mt)
            #pragma unroll
            for (int nt = 0; nt < 4; ++nt) {
                int row = mt * 16 + (lane >> 2);
                int col = w * 32 + nt * 8 + (lane & 3) * 2;
                float2 v0 = *(const float2*)(XSf + row * 132 + col);
                float2 v1 = *(const float2*)(XSf + (row + 8) * 132 + col);
                acc[mt][nt][0] = v0.x; acc[mt][nt][1] = v0.y;
                acc[mt][nt][2] = v1.x; acc[mt][nt][3] = v1.y;
            }

        // 48 HMMA: hi*hi + lo*hi + hi*lo
        #pragma unroll
        for (int mt = 0; mt < 2; ++mt)
            #pragma unroll
            for (int ks = 0; ks < 2; ++ks)
                #pragma unroll
                for (int nt = 0; nt < 4; ++nt) {
                    mma16816(acc[mt][nt], Ah[mt][ks], Bh[ks][nt][0], Bh[ks][nt][1]);
                    mma16816(acc[mt][nt], Al[mt][ks], Bh[ks][nt][0], Bh[ks][nt][1]);
                    mma16816(acc[mt][nt], Ah[mt][ks], Bl[ks][nt][0], Bl[ks][nt][1]);
                }

        // STS pre-acts for gate w: [b][36]
        float* prew = pref + w * 1152;
        #pragma unroll
        for (int mt = 0; mt < 2; ++mt)
            #pragma unroll
            for (int nt = 0; nt < 4; ++nt) {
                int row = mt * 16 + (lane >> 2);
                int colp = nt * 8 + (lane & 3) * 2;
                *(float2*)(prew + row * 36 + colp) =
                    make_float2(acc[mt][nt][0], acc[mt][nt][1]);
                *(float2*)(prew + (row + 8) * 36 + colp) =
                    make_float2(acc[mt][nt][2], acc[mt][nt][3]);
            }
        __syncthreads();                     // pre ready; XS slot consumed

        if (t + 4 < TT) ldx(slot, t + 4);

        // epilogue: 8 elements (b_ep, j0..j0+7)
        {
            const float* pb = pref + b_ep * 36 + j0;
            float4 f0 = *(const float4*)(pb);
            float4 f1 = *(const float4*)(pb + 4);
            float4 i0 = *(const float4*)(pb + 1152);
            float4 i1 = *(const float4*)(pb + 1156);
            float4 o0 = *(const float4*)(pb + 2304);
            float4 o1 = *(const float4*)(pb + 2308);
            float4 z0 = *(const float4*)(pb + 3456);
            float4 z1 = *(const float4*)(pb + 3460);
            float fT[8] = {f0.x,f0.y,f0.z,f0.w,f1.x,f1.y,f1.z,f1.w};
            float iT[8] = {i0.x,i0.y,i0.z,i0.w,i1.x,i1.y,i1.z,i1.w};
            float oT[8] = {o0.x,o0.y,o0.z,o0.w,o1.x,o1.y,o1.z,o1.w};
            float zT[8] = {z0.x,z0.y,z0.z,z0.w,z1.x,z1.y,z1.z,z1.w};
            #pragma unroll
            for (int e = 0; e < 8; ++e) {
                float fh = __expf(fminf(fT[e], 10.f));
                float ih = __expf(fminf(iT[e], 10.f));
                float rden = __fdividef(1.f, fh + ih + 1e-8f);
                float f  = fh * rden;
                float ii = ih * rden;
                float o  = 0.5f + 0.5f * tanh_hw(0.5f * oT[e]);
                float z  = tanh_hw(zT[e]);
                cst[e] = f * cst[e] + ii * z;
                nst[e] = f * nst[e] + ii;
                h[e] = o * __fdividef(cst[e], nst[e] + 1e-8f);
            }
            // h -> bf16 hi/lo
            u32 hh[4], hl[4];
            #pragma unroll
            for (int p = 0; p < 4; ++p) {
                __nv_bfloat162 hi2 = __floats2bfloat162_rn(h[2*p], h[2*p+1]);
                __nv_bfloat162 lo2 = __floats2bfloat162_rn(
                    h[2*p]   - __bfloat162float(hi2.x),
                    h[2*p+1] - __bfloat162float(hi2.y));
                hh[p] = *(u32*)&hi2; hl[p] = *(u32*)&lo2;
            }
            *(uint4*)(sm + HHI + b_ep * 80 + j0 * 2) = make_uint4(hh[0],hh[1],hh[2],hh[3]);
            *(uint4*)(sm + HLO + b_ep * 80 + j0 * 2) = make_uint4(hl[0],hl[1],hl[2],hl[3]);
        }
        asm volatile("cp.async.wait_group 3;" ::: "memory");
        __syncthreads();                     // h published; next slot arrived
    }

    // ---- head: tanh(fc_w . [h, emb[ticker]] + fc_b) ----
    float v = 0.f;
    #pragma unroll
    for (int e = 0; e < 8; ++e) v += fcw[j0 + e] * h[e];
    v += __shfl_xor_sync(0xffffffffu, v, 1);
    v += __shfl_xor_sync(0xffffffffu, v, 2);
    if ((lane & 3) == 0) {
        const int b = bat0 + b_ep;
        const int* p32 = (const int*)tick;
        bool is64 = ((p32[1] | p32[3] | p32[5] | p32[7] |
                      p32[9] | p32[11] | p32[13] | p32[15]) == 0);
        long long id = is64 ? ((const long long*)tick)[b] : (long long)p32[b];
        float ve = 0.f;
        #pragma unroll
        for (int e = 0; e < 8; ++e) ve += fcw[32 + e] * emb[id * 8 + e];
        out[b] = tanhf(v + ve + fcb[0]);
    }
}

// =====================================================================
extern "C" void kernel_launch(void* const* d_in, const int* in_sizes, int n_in,
                              void* d_out, int out_size) {
    const float* x   = (const float*)d_in[0];
    const void*  tid = d_in[1];
    const float* wf  = (const float*)d_in[2];
    const float* wfb = (const float*)d_in[3];
    const float* wi  = (const float*)d_in[4];
    const float* wib = (const float*)d_in[5];
    const float* wo  = (const float*)d_in[6];
    const float* wob = (const float*)d_in[7];
    const float* wz  = (const float*)d_in[8];
    const float* wzb = (const float*)d_in[9];
    const float* rf  = (const float*)d_in[10];
    const float* ri  = (const float*)d_in[11];
    const float* ro  = (const float*)d_in[12];
    const float* rz  = (const float*)d_in[13];
    const float* emb = (const float*)d_in[14];
    const float* fcw = (const float*)d_in[15];
    const float* fcb = (const float*)d_in[16];
    float* out = (float*)d_out;

    cudaFuncSetAttribute(proj_mma,
                         cudaFuncAttributeMaxDynamicSharedMemorySize, PJ_SMEM);
    cudaFuncSetAttribute(scan_hmma,
                         cudaFuncAttributeMaxDynamicSharedMemorySize, SC_SMEM);

    proj_mma<<<(BB * TT) / (128 * 8), 256, PJ_SMEM>>>(
        x, wf, wfb, wi, wib, wo, wob, wz, wzb);
    scan_hmma<<<BB / BPC, 128, SC_SMEM>>>(
        rf, ri, ro, rz, tid, emb, fcw, fcb, out);
}